// round 2
// baseline (speedup 1.0000x reference)
#include <cuda_runtime.h>
#include <cstdint>

// out[dst[e], :] += w[e] * x[src[e], :]
// x: [N, 64] f32; edge_weight: [E] f32; edge_index: [2, E] int32 (JAX x64 off!); out: [N, 64] f32
//
// 16 threads per edge, one float4 (16B) chunk each. Vector reduction via
// red.global.add.v4.f32 (sm_90+): 1 L2 atomic op per 16B instead of 4 scalar ones.

static constexpr int F = 64;
static constexpr int CHUNKS = F / 4;       // 16 float4 chunks per row
static constexpr int THREADS = 256;

__global__ void __launch_bounds__(THREADS)
mp_scatter_kernel(const float* __restrict__ x,
                  const float* __restrict__ ew,
                  const int* __restrict__ ei,   // [2, E] int32
                  float* __restrict__ out,
                  int E)
{
    int idx = blockIdx.x * THREADS + threadIdx.x;     // E*16 = 16M < 2^31
    int total = E * CHUNKS;
    if (idx >= total) return;

    int e = idx >> 4;          // edge id
    int c = idx & 15;          // chunk id within row

    // Same-address loads across the 16 threads of an edge -> warp broadcast.
    int s = __ldg(&ei[e]);
    int d = __ldg(&ei[E + e]);
    float w = __ldg(&ew[e]);

    const float4 v = *reinterpret_cast<const float4*>(x + (long long)s * F + c * 4);
    float4 m;
    m.x = v.x * w; m.y = v.y * w; m.z = v.z * w; m.w = v.w * w;

    float* dst = out + (long long)d * F + c * 4;
    asm volatile("red.global.add.v4.f32 [%0], {%1, %2, %3, %4};"
                 :: "l"(dst), "f"(m.x), "f"(m.y), "f"(m.z), "f"(m.w)
                 : "memory");
}

extern "C" void kernel_launch(void* const* d_in, const int* in_sizes, int n_in,
                              void* d_out, int out_size)
{
    // metadata order: x [N*F] f32, edge_weight [E] f32, edge_index [2*E] i32, num_nodes scalar
    const float* x  = (const float*)d_in[0];
    const float* ew = (const float*)d_in[1];
    const int*   ei = (const int*)d_in[2];
    float* out = (float*)d_out;

    int E = in_sizes[2] / 2;             // edge_index holds 2*E elements

    // Output is poisoned; zero it (graph-capturable memset node).
    cudaMemsetAsync(out, 0, (size_t)out_size * sizeof(float), 0);

    int total = E * CHUNKS;
    int blocks = (total + THREADS - 1) / THREADS;
    mp_scatter_kernel<<<blocks, THREADS>>>(x, ew, ei, out, E);
}